// round 12
// baseline (speedup 1.0000x reference)
#include <cuda_runtime.h>
#include <cuda_fp16.h>
#include <math.h>
#include <stdint.h>

#define BATCH 4
#define SEQ   2048
#define DIN   1024
#define HID   1024
#define NHEAD 16
#define DK    64

// Q projection scale: (1/sqrt(64)) * log2(e)  -> scores in log2 domain
#define QSCALE 0.1803368801111244f
#define ONES_H2 0x3C003C00u

// ---------------- scratch (static device globals) ----------------
__device__ __half g_x[(size_t)BATCH * SEQ * DIN];
__device__ __half g_w[(size_t)4 * HID * DIN];

__device__ __half g_q[(size_t)BATCH * NHEAD * SEQ * DK];
__device__ __half g_k[(size_t)BATCH * NHEAD * SEQ * DK];
__device__ __half g_vt[(size_t)BATCH * NHEAD * DK * SEQ];  // [bh][d][s]

__device__ __half g_ctx[(size_t)BATCH * SEQ * HID];

// ---------------------------------------------------------------------------
__device__ __forceinline__ uint32_t pack_h2(float x, float y) {
    __half2 h = __floats2half2_rn(x, y);
    return *(uint32_t*)&h;
}

__device__ __forceinline__ uint32_t cvt_f16x2(float x, float y) {
    uint32_t r;
    asm("cvt.rn.f16x2.f32 %0, %1, %2;" : "=r"(r) : "f"(y), "f"(x));
    return r;
}

__device__ __forceinline__ uint32_t ex2_h2(uint32_t x) {
    uint32_t r;
    asm("ex2.approx.f16x2 %0, %1;" : "=r"(r) : "r"(x));
    return r;
}

// ---------------------------------------------------------------------------
// fp32 -> fp16 conversions
// ---------------------------------------------------------------------------
__global__ __launch_bounds__(256) void cvt_h(
    const float4* __restrict__ x, __half2* __restrict__ dst, int n4)
{
    int i = blockIdx.x * blockDim.x + threadIdx.x;
    if (i >= n4) return;
    float4 v = x[i];
    dst[2 * i + 0] = __floats2half2_rn(v.x, v.y);
    dst[2 * i + 1] = __floats2half2_rn(v.z, v.w);
}

__global__ __launch_bounds__(256) void cvt_w4(
    const float4* __restrict__ w0, const float4* __restrict__ w1,
    const float4* __restrict__ w2, const float4* __restrict__ w3,
    __half2* __restrict__ dst)
{
    int i = blockIdx.x * blockDim.x + threadIdx.x;
    const int sel = i >> 18;
    const int j   = i & 0x3FFFF;
    const float4* src = (sel == 0) ? w0 : (sel == 1) ? w1 : (sel == 2) ? w2 : w3;
    float4 v = src[j];
    dst[2 * i + 0] = __floats2half2_rn(v.x, v.y);
    dst[2 * i + 1] = __floats2half2_rn(v.z, v.w);
}

// ---------------------------------------------------------------------------
// MMA / ldmatrix / cp.async primitives (fp16)
// ---------------------------------------------------------------------------
#define MMA_F16(d, a, b0v, b1v)                                               \
    asm volatile(                                                             \
        "mma.sync.aligned.m16n8k16.row.col.f32.f16.f16.f32 "                  \
        "{%0,%1,%2,%3}, {%4,%5,%6,%7}, {%8,%9}, {%0,%1,%2,%3};"               \
        : "+f"(d[0]), "+f"(d[1]), "+f"(d[2]), "+f"(d[3])                      \
        : "r"(a[0]), "r"(a[1]), "r"(a[2]), "r"(a[3]), "r"(b0v), "r"(b1v))

#define LDMATRIX_X4(r0, r1, r2, r3, addr)                                     \
    asm volatile("ldmatrix.sync.aligned.m8n8.x4.shared.b16 {%0,%1,%2,%3}, [%4];" \
                 : "=r"(r0), "=r"(r1), "=r"(r2), "=r"(r3) : "r"(addr))

__device__ __forceinline__ void cp_async16(uint32_t dst, const void* src) {
    asm volatile("cp.async.cg.shared.global [%0], [%1], 16;" :: "r"(dst), "l"(src));
}

// ---------------------------------------------------------------------------
// fp16 single-MMA GEMM, 128x256 CTA tile, 64x64 warp tiles (MMA-bound shape).
// C[m][n] = (sum_k A[m][k]*W[n][k] + bias[n])*scale
//   fused=1: gridDim.z = 3 -> {Q (QSCALE, mode0), K (mode0), V (mode2)}
//   fused=0: fp32 row-major output (mode1)
// BK=64 (128B rows). Stage (48KB): A(16K) W(32K). 3 stages = 144KB. 1 CTA/SM.
// ---------------------------------------------------------------------------
#define S_A 0
#define S_W 16384
#define STAGE_BYTES 49152
#define G_NSTAGE 3
#define G_SMEM (G_NSTAGE * STAGE_BYTES)   // 147456

__global__ __launch_bounds__(256, 1) void gemm_f16(
    const __half* __restrict__ A, const __half* __restrict__ Wb,
    const float* __restrict__ bias0, const float* __restrict__ bias1,
    const float* __restrict__ bias2,
    __half* __restrict__ oq, __half* __restrict__ ok, __half* __restrict__ ovt,
    float* __restrict__ fdst,
    int M, int N, int K, int fused)
{
    extern __shared__ __align__(16) char smem[];
    const uint32_t sbase = (uint32_t)__cvta_generic_to_shared(smem);

    const int z = blockIdx.z;
    const __half* W = Wb + (size_t)z * HID * DIN;
    const float* bias = (z == 0) ? bias0 : (z == 1) ? bias1 : bias2;
    __half* dsth = (z == 0) ? oq : (z == 1) ? ok : ovt;
    const int mode = fused ? ((z == 2) ? 2 : 0) : 1;
    const float scale = (fused && z == 0) ? QSCALE : 1.0f;

    const int tid    = threadIdx.x;
    const int lane   = tid & 31;
    const int wid    = tid >> 5;
    const int warp_m = wid >> 2;   // 0..1  (64 rows each)
    const int warp_n = wid & 3;    // 0..3  (64 cols each)
    const int row0   = blockIdx.y * 128;
    const int col0   = blockIdx.x * 256;

    // A loader: 128 rows x 128B, 2 threads/row, 4 chunks each
    const int lrow = tid >> 1;
    const int lcb  = (tid & 1) * 4;
    // W loader: 256 rows x 128B, 1 thread/row, 8 chunks

    float acc[4][8][4];
#pragma unroll
    for (int i = 0; i < 4; i++)
#pragma unroll
        for (int j = 0; j < 8; j++)
#pragma unroll
            for (int r = 0; r < 4; r++) acc[i][j][r] = 0.0f;

    const int NS = K >> 6;   // 16

    auto load_stage = [&](int s, int buf) {
        const int k0 = s << 6;
        const uint32_t st = sbase + buf * STAGE_BYTES;
#pragma unroll
        for (int cc = 0; cc < 4; cc++) {
            const int c  = lcb + cc;
            const int sc = c ^ (lrow & 7);
            const size_t ga = (size_t)(row0 + lrow) * K + k0 + c * 8;
            cp_async16(st + S_A + lrow * 128 + sc * 16, A + ga);
        }
#pragma unroll
        for (int c = 0; c < 8; c++) {
            const int sc = c ^ (tid & 7);
            const size_t gb = (size_t)(col0 + tid) * K + k0 + c * 8;
            cp_async16(st + S_W + tid * 128 + sc * 16, W + gb);
        }
        asm volatile("cp.async.commit_group;");
    };

    load_stage(0, 0);
    load_stage(1, 1);

    const int a_mrow = warp_m * 64 + (lane & 15);
    const int a_half = lane >> 4;
    const int b_nrow = warp_n * 64 + (lane & 7) + ((lane >> 4) << 3);
    const int b_half = (lane >> 3) & 1;

    for (int s = 0; s < NS; s++) {
        if (s + 2 < NS) {
            load_stage(s + 2, (s + 2) % G_NSTAGE);
            asm volatile("cp.async.wait_group 2;");
        } else if (s + 1 < NS) {
            asm volatile("cp.async.wait_group 1;");
        } else {
            asm volatile("cp.async.wait_group 0;");
        }
        __syncthreads();

        const uint32_t st = sbase + (s % G_NSTAGE) * STAGE_BYTES;

#pragma unroll
        for (int ks = 0; ks < 4; ks++) {
            uint32_t af[4][4], bw[8][2];
#pragma unroll
            for (int mi = 0; mi < 4; mi++) {
                const int mr = a_mrow + mi * 16;
                const int c  = ks * 2 + a_half;
                const int sc = c ^ (mr & 7);
                LDMATRIX_X4(af[mi][0], af[mi][1], af[mi][2], af[mi][3],
                            st + S_A + mr * 128 + sc * 16);
            }
#pragma unroll
            for (int bi = 0; bi < 4; bi++) {
                const int nr = b_nrow + bi * 16;
                const int c  = ks * 2 + b_half;
                const int sc = c ^ (nr & 7);
                uint32_t r0, r1, r2, r3;
                LDMATRIX_X4(r0, r1, r2, r3, st + S_W + nr * 128 + sc * 16);
                bw[2 * bi + 0][0] = r0; bw[2 * bi + 0][1] = r1;
                bw[2 * bi + 1][0] = r2; bw[2 * bi + 1][1] = r3;
            }
#pragma unroll
            for (int mi = 0; mi < 4; mi++)
#pragma unroll
                for (int ni = 0; ni < 8; ni++)
                    MMA_F16(acc[mi][ni], af[mi], bw[ni][0], bw[ni][1]);
        }
        __syncthreads();
    }

    // epilogue
    const int erow = lane >> 2;
    const int ecol = (lane & 3) * 2;
#pragma unroll
    for (int mi = 0; mi < 4; mi++) {
#pragma unroll
        for (int ni = 0; ni < 8; ni++) {
            const int mbase = row0 + warp_m * 64 + mi * 16 + erow;
            const int nbase = col0 + warp_n * 64 + ni * 8 + ecol;
#pragma unroll
            for (int rr = 0; rr < 2; rr++) {
                const int m = mbase + rr * 8;
                const int n = nbase;
                const float c0 = (acc[mi][ni][rr * 2 + 0] + bias[n])     * scale;
                const float c1 = (acc[mi][ni][rr * 2 + 1] + bias[n + 1]) * scale;
                if (mode == 1) {
                    fdst[(size_t)m * N + n]     = c0;
                    fdst[(size_t)m * N + n + 1] = c1;
                } else {
                    const int b_ = m / SEQ, s_ = m % SEQ;
                    const int h_ = n / DK,  d_ = n % DK;
                    if (mode == 0) {
                        const size_t idx =
                            (((size_t)b_ * NHEAD + h_) * SEQ + s_) * DK + d_;
                        *(uint32_t*)(dsth + idx) = pack_h2(c0, c1);
                    } else {   // transposed [bh][d][s]
                        const size_t idx =
                            (((size_t)b_ * NHEAD + h_) * DK + d_) * SEQ + s_;
                        dsth[idx]       = __float2half_rn(c0);
                        dsth[idx + SEQ] = __float2half_rn(c1);
                    }
                }
            }
        }
    }
}

// ---------------------------------------------------------------------------
// fp16 flash attention (unchanged from round 11): 128-q tiles, 2 CTA/SM,
// packed f16x2 exp2 softmax, l via ones-MMA.
// smem: Q (16KB) + 2 stages x (K 8KB + Vt 8KB) = 48KB
// ---------------------------------------------------------------------------
#define AQ 0
#define AST_BASE 16384
#define AST_SZ 16384
#define AK 0
#define AV 8192
#define A_SMEM (AST_BASE + 2 * AST_SZ)    // 49152

__global__ __launch_bounds__(256, 2) void flash_attn_f16(
    const __half* __restrict__ q, const __half* __restrict__ k,
    const __half* __restrict__ vt, __half* __restrict__ ctx)
{
    extern __shared__ __align__(16) char smem[];
    const uint32_t sbase = (uint32_t)__cvta_generic_to_shared(smem);

    const int tid  = threadIdx.x;
    const int lane = tid & 31;
    const int wid  = tid >> 5;

    const int bh = blockIdx.y;
    const int q0 = blockIdx.x * 128;

    const __half* Qb = q  + (size_t)bh * SEQ * DK;
    const __half* Kb = k  + (size_t)bh * SEQ * DK;
    const __half* Vb = vt + (size_t)bh * DK * SEQ;

    const int lrowQ = tid >> 1;
    const int lcbQ  = (tid & 1) * 4;
    const int lrowS = tid >> 2;
    const int lcbS  = (tid & 3) * 2;

    {
#pragma unroll
        for (int cc = 0; cc < 4; cc++) {
            const int c  = lcbQ + cc;
            const int sc = c ^ (lrowQ & 7);
            const size_t gq = (size_t)(q0 + lrowQ) * DK + c * 8;
            cp_async16(sbase + AQ + lrowQ * 128 + sc * 16, Qb + gq);
        }
        const uint32_t st = sbase + AST_BASE;
#pragma unroll
        for (int cc = 0; cc < 2; cc++) {
            const int c  = lcbS + cc;
            const int sc = c ^ (lrowS & 7);
            const size_t gk = (size_t)lrowS * DK + c * 8;
            const size_t gv = (size_t)lrowS * SEQ + c * 8;
            cp_async16(st + AK + lrowS * 128 + sc * 16, Kb + gk);
            cp_async16(st + AV + lrowS * 128 + sc * 16, Vb + gv);
        }
        asm volatile("cp.async.commit_group;");
    }

    float oacc[8][4];
    float lacc[4];
#pragma unroll
    for (int i = 0; i < 8; i++)
#pragma unroll
        for (int j = 0; j < 4; j++) oacc[i][j] = 0.0f;
#pragma unroll
    for (int j = 0; j < 4; j++) lacc[j] = 0.0f;

    const int a_mrow  = wid * 16 + (lane & 15);
    const int a_half  = lane >> 4;
    const int b_nrow0 = (lane & 7) + ((lane >> 4) << 3);
    const int b_half  = (lane >> 3) & 1;

    const int NT = SEQ / 64;   // 32
    for (int t = 0; t < NT; t++) {
        if (t + 1 < NT) {
            const int kb = (t + 1) * 64;
            const uint32_t st = sbase + AST_BASE + ((t + 1) & 1) * AST_SZ;
#pragma unroll
            for (int cc = 0; cc < 2; cc++) {
                const int c  = lcbS + cc;
                const int sc = c ^ (lrowS & 7);
                const size_t gk = (size_t)(kb + lrowS) * DK + c * 8;
                const size_t gv = (size_t)lrowS * SEQ + kb + c * 8;
                cp_async16(st + AK + lrowS * 128 + sc * 16, Kb + gk);
                cp_async16(st + AV + lrowS * 128 + sc * 16, Vb + gv);
            }
            asm volatile("cp.async.commit_group;");
            asm volatile("cp.async.wait_group 1;");
        } else {
            asm volatile("cp.async.wait_group 0;");
        }
        __syncthreads();

        const uint32_t st = sbase + AST_BASE + (t & 1) * AST_SZ;

        // ---- S = Q K^T (log2 domain) ----
        float sacc[8][4];
#pragma unroll
        for (int i = 0; i < 8; i++)
#pragma unroll
            for (int j = 0; j < 4; j++) sacc[i][j] = 0.0f;

#pragma unroll
        for (int ks = 0; ks < 4; ks++) {
            uint32_t aq[4];
            {
                const int c  = ks * 2 + a_half;
                const int sc = c ^ (a_mrow & 7);
                LDMATRIX_X4(aq[0], aq[1], aq[2], aq[3],
                            sbase + AQ + a_mrow * 128 + sc * 16);
            }
#pragma unroll
            for (int bi = 0; bi < 4; bi++) {
                const int nr = b_nrow0 + bi * 16;
                const int c  = ks * 2 + b_half;
                const int sc = c ^ (nr & 7);
                uint32_t h0, h1, h2, h3;
                LDMATRIX_X4(h0, h1, h2, h3, st + AK + nr * 128 + sc * 16);
                MMA_F16(sacc[2 * bi + 0], aq, h0, h1);
                MMA_F16(sacc[2 * bi + 1], aq, h2, h3);
            }
        }

        // ---- P = exp2(S) packed fp16x2 ----
        uint32_t pp[8][2];
#pragma unroll
        for (int nt = 0; nt < 8; nt++) {
            pp[nt][0] = ex2_h2(cvt_f16x2(sacc[nt][0], sacc[nt][1]));
            pp[nt][1] = ex2_h2(cvt_f16x2(sacc[nt][2], sacc[nt][3]));
        }

        // ---- O += P V ; l += P * ones (MMA, fp32 acc) ----
#pragma unroll
        for (int ks = 0; ks < 4; ks++) {
            uint32_t ph[4];
            ph[0] = pp[2 * ks + 0][0];
            ph[1] = pp[2 * ks + 0][1];
            ph[2] = pp[2 * ks + 1][0];
            ph[3] = pp[2 * ks + 1][1];
            MMA_F16(lacc, ph, ONES_H2, ONES_H2);
#pragma unroll
            for (int bi = 0; bi < 4; bi++) {
                const int nr = b_nrow0 + bi * 16;
                const int c  = ks * 2 + b_half;
                const int sc = c ^ (nr & 7);
                uint32_t h0, h1, h2, h3;
                LDMATRIX_X4(h0, h1, h2, h3, st + AV + nr * 128 + sc * 16);
                MMA_F16(oacc[2 * bi + 0], ph, h0, h1);
                MMA_F16(oacc[2 * bi + 1], ph, h2, h3);
            }
        }
        __syncthreads();
    }

    // ---- epilogue ----
    const float inv0 = 1.0f / lacc[0];
    const float inv1 = 1.0f / lacc[2];
    const int b_ = bh >> 4;
    const int h_ = bh & 15;
    const int r0g = q0 + wid * 16 + (lane >> 2);
    const int r1g = r0g + 8;
    const size_t row0 = ((size_t)b_ * SEQ + r0g) * HID + h_ * DK;
    const size_t row1 = ((size_t)b_ * SEQ + r1g) * HID + h_ * DK;
#pragma unroll
    for (int nt = 0; nt < 8; nt++) {
        const int d = nt * 8 + (lane & 3) * 2;
        *(uint32_t*)(ctx + row0 + d) = pack_h2(oacc[nt][0] * inv0,
                                               oacc[nt][1] * inv0);
        *(uint32_t*)(ctx + row1 + d) = pack_h2(oacc[nt][2] * inv1,
                                               oacc[nt][3] * inv1);
    }
}

// ---------------------------------------------------------------------------
extern "C" void kernel_launch(void* const* d_in, const int* in_sizes, int n_in,
                              void* d_out, int out_size)
{
    const float* X  = (const float*)d_in[0];
    const float* Wq = (const float*)d_in[1];
    const float* bq = (const float*)d_in[2];
    const float* Wk = (const float*)d_in[3];
    const float* bk = (const float*)d_in[4];
    const float* Wv = (const float*)d_in[5];
    const float* bv = (const float*)d_in[6];
    const float* Wo = (const float*)d_in[7];
    const float* bo = (const float*)d_in[8];
    float* out = (float*)d_out;

    __half *x, *w, *ctx, *qb, *kb, *vtb;
    cudaGetSymbolAddress((void**)&x,   g_x);
    cudaGetSymbolAddress((void**)&w,   g_w);
    cudaGetSymbolAddress((void**)&ctx, g_ctx);
    cudaGetSymbolAddress((void**)&qb,  g_q);
    cudaGetSymbolAddress((void**)&kb,  g_k);
    cudaGetSymbolAddress((void**)&vtb, g_vt);

    cudaFuncSetAttribute(gemm_f16,
                         cudaFuncAttributeMaxDynamicSharedMemorySize, G_SMEM);
    cudaFuncSetAttribute(flash_attn_f16,
                         cudaFuncAttributeMaxDynamicSharedMemorySize, A_SMEM);

    const int M = BATCH * SEQ;            // 8192
    const size_t WSZ = (size_t)HID * DIN;

    {
        const int nx4 = M * DIN / 4;
        cvt_h<<<(nx4 + 255) / 256, 256>>>((const float4*)X, (__half2*)x, nx4);
        const int nw4 = (int)(4 * WSZ / 4);   // 2^20
        cvt_w4<<<nw4 / 256, 256>>>(
            (const float4*)Wq, (const float4*)Wk,
            (const float4*)Wv, (const float4*)Wo, (__half2*)w);
    }

    dim3 gqkv(HID / 256, M / 128, 3);       // (4, 64, 3) fused Q/K/V
    dim3 gout(HID / 256, M / 128, 1);       // (4, 64)
    dim3 gattn(SEQ / 128, BATCH * NHEAD);   // (16, 64)

    gemm_f16<<<gqkv, 256, G_SMEM>>>(
        x, w, bq, bk, bv, qb, kb, vtb, nullptr, M, HID, DIN, 1);

    flash_attn_f16<<<gattn, 256, A_SMEM>>>(qb, kb, vtb, ctx);

    gemm_f16<<<gout, 256, G_SMEM>>>(
        ctx, w + 3 * WSZ, bo, nullptr, nullptr,
        nullptr, nullptr, nullptr, out, M, HID, HID, 0);
}

// round 13
// speedup vs baseline: 1.3000x; 1.3000x over previous
#include <cuda_runtime.h>
#include <cuda_fp16.h>
#include <math.h>
#include <stdint.h>

#define BATCH 4
#define SEQ   2048
#define DIN   1024
#define HID   1024
#define NHEAD 16
#define DK    64

// Q projection scale: (1/sqrt(64)) * log2(e)  -> scores in log2 domain
#define QSCALE 0.1803368801111244f
#define ONES_H2 0x3C003C00u

// ---------------- scratch (static device globals) ----------------
__device__ __half g_x[(size_t)BATCH * SEQ * DIN];
__device__ __half g_w[(size_t)4 * HID * DIN];

__device__ __half g_q[(size_t)BATCH * NHEAD * SEQ * DK];
__device__ __half g_k[(size_t)BATCH * NHEAD * SEQ * DK];
__device__ __half g_vt[(size_t)BATCH * NHEAD * DK * SEQ];  // [bh][d][s]

__device__ __half g_ctx[(size_t)BATCH * SEQ * HID];

// ---------------------------------------------------------------------------
__device__ __forceinline__ uint32_t pack_h2(float x, float y) {
    __half2 h = __floats2half2_rn(x, y);
    return *(uint32_t*)&h;
}

__device__ __forceinline__ uint32_t cvt_f16x2(float x, float y) {
    uint32_t r;
    asm("cvt.rn.f16x2.f32 %0, %1, %2;" : "=r"(r) : "f"(y), "f"(x));
    return r;
}

__device__ __forceinline__ uint32_t ex2_h2(uint32_t x) {
    uint32_t r;
    asm("ex2.approx.f16x2 %0, %1;" : "=r"(r) : "r"(x));
    return r;
}

// ---------------------------------------------------------------------------
// fused fp32 -> fp16 conversion: X (2^21 float4) then 4 weight mats (2^18 each)
// ---------------------------------------------------------------------------
__global__ __launch_bounds__(256) void cvt_all(
    const float4* __restrict__ x,
    const float4* __restrict__ w0, const float4* __restrict__ w1,
    const float4* __restrict__ w2, const float4* __restrict__ w3,
    __half2* __restrict__ dx, __half2* __restrict__ dw)
{
    const int i = blockIdx.x * blockDim.x + threadIdx.x;  // 0 .. 3*2^20-1
    const float4* src;
    __half2* dst;
    int j;
    if (i < (1 << 21)) {
        src = x; dst = dx; j = i;
    } else {
        const int t = i - (1 << 21);
        const int sel = t >> 18;
        j = t & 0x3FFFF;
        src = (sel == 0) ? w0 : (sel == 1) ? w1 : (sel == 2) ? w2 : w3;
        dst = dw + (size_t)sel * (1 << 19);
    }
    float4 v = src[j];
    dst[2 * j + 0] = __floats2half2_rn(v.x, v.y);
    dst[2 * j + 1] = __floats2half2_rn(v.z, v.w);
}

// ---------------------------------------------------------------------------
// MMA / ldmatrix / cp.async primitives (fp16)
// ---------------------------------------------------------------------------
#define MMA_F16(d, a, b0v, b1v)                                               \
    asm volatile(                                                             \
        "mma.sync.aligned.m16n8k16.row.col.f32.f16.f16.f32 "                  \
        "{%0,%1,%2,%3}, {%4,%5,%6,%7}, {%8,%9}, {%0,%1,%2,%3};"               \
        : "+f"(d[0]), "+f"(d[1]), "+f"(d[2]), "+f"(d[3])                      \
        : "r"(a[0]), "r"(a[1]), "r"(a[2]), "r"(a[3]), "r"(b0v), "r"(b1v))

#define LDMATRIX_X4(r0, r1, r2, r3, addr)                                     \
    asm volatile("ldmatrix.sync.aligned.m8n8.x4.shared.b16 {%0,%1,%2,%3}, [%4];" \
                 : "=r"(r0), "=r"(r1), "=r"(r2), "=r"(r3) : "r"(addr))

__device__ __forceinline__ void cp_async16(uint32_t dst, const void* src) {
    asm volatile("cp.async.cg.shared.global [%0], [%1], 16;" :: "r"(dst), "l"(src));
}

// ---------------------------------------------------------------------------
// fp16 single-MMA GEMM (round-11 shape: 128x128 CTA, 64x32 warp tiles,
// 2 CTA/SM) with single-sync 3-stage pipeline (prefetch after compute).
//   fused=1: gridDim.z = 3 -> {Q (QSCALE, mode0), K (mode0), V (mode2)}
//   fused=0: fp32 row-major output (mode1)
// BK=64 (128B rows). Stage (32KB): A(16K) W(16K). 3 stages = 96KB.
// ---------------------------------------------------------------------------
#define S_A 0
#define S_W 16384
#define STAGE_BYTES 32768
#define G_NSTAGE 3
#define G_SMEM (G_NSTAGE * STAGE_BYTES)   // 98304

__global__ __launch_bounds__(256, 2) void gemm_f16(
    const __half* __restrict__ A, const __half* __restrict__ Wb,
    const float* __restrict__ bias0, const float* __restrict__ bias1,
    const float* __restrict__ bias2,
    __half* __restrict__ oq, __half* __restrict__ ok, __half* __restrict__ ovt,
    float* __restrict__ fdst,
    int M, int N, int K, int fused)
{
    extern __shared__ __align__(16) char smem[];
    const uint32_t sbase = (uint32_t)__cvta_generic_to_shared(smem);

    const int z = blockIdx.z;
    const __half* W = Wb + (size_t)z * HID * DIN;
    const float* bias = (z == 0) ? bias0 : (z == 1) ? bias1 : bias2;
    __half* dsth = (z == 0) ? oq : (z == 1) ? ok : ovt;
    const int mode = fused ? ((z == 2) ? 2 : 0) : 1;
    const float scale = (fused && z == 0) ? QSCALE : 1.0f;

    const int tid    = threadIdx.x;
    const int lane   = tid & 31;
    const int wid    = tid >> 5;
    const int warp_m = wid >> 2;
    const int warp_n = wid & 3;
    const int row0   = blockIdx.y * 128;
    const int col0   = blockIdx.x * 128;

    const int lrow = tid >> 1;
    const int lcb  = (tid & 1) * 4;

    float acc[4][4][4];
#pragma unroll
    for (int i = 0; i < 4; i++)
#pragma unroll
        for (int j = 0; j < 4; j++)
#pragma unroll
            for (int r = 0; r < 4; r++) acc[i][j][r] = 0.0f;

    const int NS = K >> 6;   // 16

    auto load_stage = [&](int s, int buf) {
        const int k0 = s << 6;
        const uint32_t st = sbase + buf * STAGE_BYTES;
#pragma unroll
        for (int cc = 0; cc < 4; cc++) {
            const int c  = lcb + cc;
            const int sc = c ^ (lrow & 7);
            const size_t ga = (size_t)(row0 + lrow) * K + k0 + c * 8;
            const size_t gb = (size_t)(col0 + lrow) * K + k0 + c * 8;
            cp_async16(st + S_A + lrow * 128 + sc * 16, A + ga);
            cp_async16(st + S_W + lrow * 128 + sc * 16, W + gb);
        }
        asm volatile("cp.async.commit_group;");
    };

    load_stage(0, 0);
    load_stage(1, 1);

    const int a_mrow = warp_m * 64 + (lane & 15);
    const int a_half = lane >> 4;
    const int b_nrow = warp_n * 32 + (lane & 7) + ((lane >> 4) << 3);
    const int b_half = (lane >> 3) & 1;

    for (int s = 0; s < NS; s++) {
        if (s + 1 < NS) {
            asm volatile("cp.async.wait_group 1;");
        } else {
            asm volatile("cp.async.wait_group 0;");
        }
        __syncthreads();

        const uint32_t st = sbase + (s % G_NSTAGE) * STAGE_BYTES;

#pragma unroll
        for (int ks = 0; ks < 4; ks++) {
            uint32_t af[4][4], bw[4][2];
#pragma unroll
            for (int mi = 0; mi < 4; mi++) {
                const int mr = a_mrow + mi * 16;
                const int c  = ks * 2 + a_half;
                const int sc = c ^ (mr & 7);
                LDMATRIX_X4(af[mi][0], af[mi][1], af[mi][2], af[mi][3],
                            st + S_A + mr * 128 + sc * 16);
            }
#pragma unroll
            for (int bi = 0; bi < 2; bi++) {
                const int nr = b_nrow + bi * 16;
                const int c  = ks * 2 + b_half;
                const int sc = c ^ (nr & 7);
                uint32_t r0, r1, r2, r3;
                LDMATRIX_X4(r0, r1, r2, r3, st + S_W + nr * 128 + sc * 16);
                bw[2 * bi + 0][0] = r0; bw[2 * bi + 0][1] = r1;
                bw[2 * bi + 1][0] = r2; bw[2 * bi + 1][1] = r3;
            }
#pragma unroll
            for (int mi = 0; mi < 4; mi++)
#pragma unroll
                for (int ni = 0; ni < 4; ni++)
                    MMA_F16(acc[mi][ni], af[mi], bw[ni][0], bw[ni][1]);
        }

        // prefetch two stages ahead (buffer (s+2)%3 was fully consumed in
        // iteration s-1; the sync at the top of this iteration ordered that)
        if (s + 2 < NS) load_stage(s + 2, (s + 2) % G_NSTAGE);
    }

    // epilogue
    const int erow = lane >> 2;
    const int ecol = (lane & 3) * 2;
#pragma unroll
    for (int mi = 0; mi < 4; mi++) {
#pragma unroll
        for (int ni = 0; ni < 4; ni++) {
            const int mbase = row0 + warp_m * 64 + mi * 16 + erow;
            const int nbase = col0 + warp_n * 32 + ni * 8 + ecol;
#pragma unroll
            for (int rr = 0; rr < 2; rr++) {
                const int m = mbase + rr * 8;
                const int n = nbase;
                const float c0 = (acc[mi][ni][rr * 2 + 0] + bias[n])     * scale;
                const float c1 = (acc[mi][ni][rr * 2 + 1] + bias[n + 1]) * scale;
                if (mode == 1) {
                    fdst[(size_t)m * N + n]     = c0;
                    fdst[(size_t)m * N + n + 1] = c1;
                } else {
                    const int b_ = m / SEQ, s_ = m % SEQ;
                    const int h_ = n / DK,  d_ = n % DK;
                    if (mode == 0) {
                        const size_t idx =
                            (((size_t)b_ * NHEAD + h_) * SEQ + s_) * DK + d_;
                        *(uint32_t*)(dsth + idx) = pack_h2(c0, c1);
                    } else {   // transposed [bh][d][s]
                        const size_t idx =
                            (((size_t)b_ * NHEAD + h_) * DK + d_) * SEQ + s_;
                        dsth[idx]       = __float2half_rn(c0);
                        dsth[idx + SEQ] = __float2half_rn(c1);
                    }
                }
            }
        }
    }
}

// ---------------------------------------------------------------------------
// fp16 flash attention: 128-q tiles, 2 CTA/SM, packed f16x2 exp2 softmax,
// l via ones-MMA. Single-sync 3-stage K/V pipeline (prefetch after compute).
// smem: Q (16KB) + 3 stages x (K 8KB + Vt 8KB) = 64KB
// ---------------------------------------------------------------------------
#define AQ 0
#define AST_BASE 16384
#define AST_SZ 16384
#define A_NSTAGE 3
#define AK 0
#define AV 8192
#define A_SMEM (AST_BASE + A_NSTAGE * AST_SZ)    // 65536

__global__ __launch_bounds__(256, 2) void flash_attn_f16(
    const __half* __restrict__ q, const __half* __restrict__ k,
    const __half* __restrict__ vt, __half* __restrict__ ctx)
{
    extern __shared__ __align__(16) char smem[];
    const uint32_t sbase = (uint32_t)__cvta_generic_to_shared(smem);

    const int tid  = threadIdx.x;
    const int lane = tid & 31;
    const int wid  = tid >> 5;

    const int bh = blockIdx.y;
    const int q0 = blockIdx.x * 128;

    const __half* Qb = q  + (size_t)bh * SEQ * DK;
    const __half* Kb = k  + (size_t)bh * SEQ * DK;
    const __half* Vb = vt + (size_t)bh * DK * SEQ;

    const int lrowQ = tid >> 1;
    const int lcbQ  = (tid & 1) * 4;
    const int lrowS = tid >> 2;
    const int lcbS  = (tid & 3) * 2;

    auto load_kv = [&](int t, int buf) {
        const int kb = t * 64;
        const uint32_t st = sbase + AST_BASE + buf * AST_SZ;
#pragma unroll
        for (int cc = 0; cc < 2; cc++) {
            const int c  = lcbS + cc;
            const int sc = c ^ (lrowS & 7);
            const size_t gk = (size_t)(kb + lrowS) * DK + c * 8;
            const size_t gv = (size_t)lrowS * SEQ + kb + c * 8;
            cp_async16(st + AK + lrowS * 128 + sc * 16, Kb + gk);
            cp_async16(st + AV + lrowS * 128 + sc * 16, Vb + gv);
        }
        asm volatile("cp.async.commit_group;");
    };

    {
#pragma unroll
        for (int cc = 0; cc < 4; cc++) {
            const int c  = lcbQ + cc;
            const int sc = c ^ (lrowQ & 7);
            const size_t gq = (size_t)(q0 + lrowQ) * DK + c * 8;
            cp_async16(sbase + AQ + lrowQ * 128 + sc * 16, Qb + gq);
        }
    }
    load_kv(0, 0);   // Q rides in group 0 with stage 0
    load_kv(1, 1);

    float oacc[8][4];
    float lacc[4];
#pragma unroll
    for (int i = 0; i < 8; i++)
#pragma unroll
        for (int j = 0; j < 4; j++) oacc[i][j] = 0.0f;
#pragma unroll
    for (int j = 0; j < 4; j++) lacc[j] = 0.0f;

    const int a_mrow  = wid * 16 + (lane & 15);
    const int a_half  = lane >> 4;
    const int b_nrow0 = (lane & 7) + ((lane >> 4) << 3);
    const int b_half  = (lane >> 3) & 1;

    const int NT = SEQ / 64;   // 32
    for (int t = 0; t < NT; t++) {
        if (t + 1 < NT) {
            asm volatile("cp.async.wait_group 1;");
        } else {
            asm volatile("cp.async.wait_group 0;");
        }
        __syncthreads();

        const uint32_t st = sbase + AST_BASE + (t % A_NSTAGE) * AST_SZ;

        // ---- S = Q K^T (log2 domain) ----
        float sacc[8][4];
#pragma unroll
        for (int i = 0; i < 8; i++)
#pragma unroll
            for (int j = 0; j < 4; j++) sacc[i][j] = 0.0f;

#pragma unroll
        for (int ks = 0; ks < 4; ks++) {
            uint32_t aq[4];
            {
                const int c  = ks * 2 + a_half;
                const int sc = c ^ (a_mrow & 7);
                LDMATRIX_X4(aq[0], aq[1], aq[2], aq[3],
                            sbase + AQ + a_mrow * 128 + sc * 16);
            }
#pragma unroll
            for (int bi = 0; bi < 4; bi++) {
                const int nr = b_nrow0 + bi * 16;
                const int c  = ks * 2 + b_half;
                const int sc = c ^ (nr & 7);
                uint32_t h0, h1, h2, h3;
                LDMATRIX_X4(h0, h1, h2, h3, st + AK + nr * 128 + sc * 16);
                MMA_F16(sacc[2 * bi + 0], aq, h0, h1);
                MMA_F16(sacc[2 * bi + 1], aq, h2, h3);
            }
        }

        // ---- P = exp2(S) packed fp16x2 ----
        uint32_t pp[8][2];
#pragma unroll
        for (int nt = 0; nt < 8; nt++) {
            pp[nt][0] = ex2_h2(cvt_f16x2(sacc[nt][0], sacc[nt][1]));
            pp[nt][1] = ex2_h2(cvt_f16x2(sacc[nt][2], sacc[nt][3]));
        }

        // ---- O += P V ; l += P * ones (MMA, fp32 acc) ----
#pragma unroll
        for (int ks = 0; ks < 4; ks++) {
            uint32_t ph[4];
            ph[0] = pp[2 * ks + 0][0];
            ph[1] = pp[2 * ks + 0][1];
            ph[2] = pp[2 * ks + 1][0];
            ph[3] = pp[2 * ks + 1][1];
            MMA_F16(lacc, ph, ONES_H2, ONES_H2);
#pragma unroll
            for (int bi = 0; bi < 4; bi++) {
                const int nr = b_nrow0 + bi * 16;
                const int c  = ks * 2 + b_half;
                const int sc = c ^ (nr & 7);
                uint32_t h0, h1, h2, h3;
                LDMATRIX_X4(h0, h1, h2, h3, st + AV + nr * 128 + sc * 16);
                MMA_F16(oacc[2 * bi + 0], ph, h0, h1);
                MMA_F16(oacc[2 * bi + 1], ph, h2, h3);
            }
        }

        // prefetch two tiles ahead (buffer consumed in iteration t-1)
        if (t + 2 < NT) load_kv(t + 2, (t + 2) % A_NSTAGE);
    }

    // ---- epilogue ----
    const float inv0 = 1.0f / lacc[0];
    const float inv1 = 1.0f / lacc[2];
    const int b_ = bh >> 4;
    const int h_ = bh & 15;
    const int r0g = q0 + wid * 16 + (lane >> 2);
    const int r1g = r0g + 8;
    const size_t row0 = ((size_t)b_ * SEQ + r0g) * HID + h_ * DK;
    const size_t row1 = ((size_t)b_ * SEQ + r1g) * HID + h_ * DK;
#pragma unroll
    for (int nt = 0; nt < 8; nt++) {
        const int d = nt * 8 + (lane & 3) * 2;
        *(uint32_t*)(ctx + row0 + d) = pack_h2(oacc[nt][0] * inv0,
                                               oacc[nt][1] * inv0);
        *(uint32_t*)(ctx + row1 + d) = pack_h2(oacc[nt][2] * inv1,
                                               oacc[nt][3] * inv1);
    }
}

// ---------------------------------------------------------------------------
extern "C" void kernel_launch(void* const* d_in, const int* in_sizes, int n_in,
                              void* d_out, int out_size)
{
    const float* X  = (const float*)d_in[0];
    const float* Wq = (const float*)d_in[1];
    const float* bq = (const float*)d_in[2];
    const float* Wk = (const float*)d_in[3];
    const float* bk = (const float*)d_in[4];
    const float* Wv = (const float*)d_in[5];
    const float* bv = (const float*)d_in[6];
    const float* Wo = (const float*)d_in[7];
    const float* bo = (const float*)d_in[8];
    float* out = (float*)d_out;

    __half *x, *w, *ctx, *qb, *kb, *vtb;
    cudaGetSymbolAddress((void**)&x,   g_x);
    cudaGetSymbolAddress((void**)&w,   g_w);
    cudaGetSymbolAddress((void**)&ctx, g_ctx);
    cudaGetSymbolAddress((void**)&qb,  g_q);
    cudaGetSymbolAddress((void**)&kb,  g_k);
    cudaGetSymbolAddress((void**)&vtb, g_vt);

    cudaFuncSetAttribute(gemm_f16,
                         cudaFuncAttributeMaxDynamicSharedMemorySize, G_SMEM);
    cudaFuncSetAttribute(flash_attn_f16,
                         cudaFuncAttributeMaxDynamicSharedMemorySize, A_SMEM);

    const int M = BATCH * SEQ;            // 8192
    const size_t WSZ = (size_t)HID * DIN;

    {
        // 3 * 2^20 float4s total: X (2^21) + 4 weights (2^18 each)
        const int ntot = 3 * (1 << 20);
        cvt_all<<<ntot / 256, 256>>>(
            (const float4*)X,
            (const float4*)Wq, (const float4*)Wk,
            (const float4*)Wv, (const float4*)Wo,
            (__half2*)x, (__half2*)w);
    }

    dim3 gqkv(HID / 128, M / 128, 3);       // (8, 64, 3) fused Q/K/V
    dim3 gout(HID / 128, M / 128, 1);
    dim3 gattn(SEQ / 128, BATCH * NHEAD);   // (16, 64)

    gemm_f16<<<gqkv, 256, G_SMEM>>>(
        x, w, bq, bk, bv, qb, kb, vtb, nullptr, M, HID, DIN, 1);

    flash_attn_f16<<<gattn, 256, A_SMEM>>>(qb, kb, vtb, ctx);

    gemm_f16<<<gout, 256, G_SMEM>>>(
        ctx, w + 3 * WSZ, bo, nullptr, nullptr,
        nullptr, nullptr, nullptr, out, M, HID, HID, 0);
}